// round 14
// baseline (speedup 1.0000x reference)
#include <cuda_runtime.h>
#include <math.h>

#define S_DIM 16
#define B_DIM 128
#define T_DIM 200
#define L_DIM 64
#define R_DIM 16
#define H_DIM 256
#define NT    256
#define LP    65    // padded stride, 64x64 matrices
#define LT    68    // padded stride for LbT (float4 rows)
#define HS    260   // padded stride for hidden
#define KP    17    // padded stride for K tile

struct __align__(16) SmemNLF {
  float w1[L_DIM * H_DIM];
  float w2[H_DIM * L_DIM];
  float b1[H_DIM];
  float b2[L_DIM];
  float zs[S_DIM * L_DIM];
  float hid[S_DIM * HS];
  float ms[S_DIM * L_DIM];
  float Lb[L_DIM * LP];      // cholesky factor, row-major, zeros above diag
  float LbT[L_DIM * LT];     // transposed factor (row j = column j of L)
  float Li[L_DIM * LP];      // inverse factor, zeros above diag
  float Ksm[L_DIM * KP];
  float wsm[S_DIM * L_DIM];
  float colbuf[2][4][72];    // chol 4-column broadcast (double buffered)
  float ybuf[2][8][72];      // triinv 8-pivot broadcast (double buffered)
  float kt[L_DIM];
  float mp[L_DIM];
  float hf[L_DIM];
  float mf[L_DIM];
  float yv[L_DIM];
  float invd[L_DIM];
  float Qs[L_DIM];
  float m0s[L_DIM];
  float J0s[L_DIM];
  float sqP0[L_DIM];
};

__device__ __forceinline__ float softplus_f(float x) {
  return fmaxf(x, 0.0f) + log1pf(expf(-fabsf(x)));
}

// Register-resident right-looking Cholesky, FOUR columns per barrier.
// Thread (i, g:0..3) owns A[i][16g+q] in a[16]. Owner group broadcasts four
// raw columns; all threads redundantly factor the 4x4 pivot block from the
// broadcasts and apply a fused rank-4 register update. 16 barriers.
__device__ __forceinline__ void chol64_reg(float* a, SmemNLF* sm,
                                           const int i, const int g) {
  const int gb = g << 4;
#pragma unroll 1
  for (int jg = 0; jg < 4; ++jg) {
    const bool owner = (g == jg);
#pragma unroll
    for (int m = 0; m < 4; ++m) {
      const int j0 = (jg << 4) + (m << 2);
      float (*cb)[72] = sm->colbuf[m & 1];
      if (owner) {
        const int q0 = m << 2;
        cb[0][i] = a[q0];     cb[1][i] = a[q0 + 1];
        cb[2][i] = a[q0 + 2]; cb[3][i] = a[q0 + 3];
      }
      __syncthreads();
      // 4x4 pivot factorization (redundant on every thread, registers only)
      const float p00 = cb[0][j0], p10 = cb[0][j0+1], p20 = cb[0][j0+2], p30 = cb[0][j0+3];
      const float p11 = cb[1][j0+1], p21 = cb[1][j0+2], p31 = cb[1][j0+3];
      const float p22 = cb[2][j0+2], p32 = cb[2][j0+3], p33 = cb[3][j0+3];
      const float s0 = rsqrtf(p00), inv0 = s0 * s0;
      const float t10 = p10 * inv0, t20 = p20 * inv0, t30 = p30 * inv0;
      const float d1 = p11 - p10 * t10;
      const float s1 = rsqrtf(d1), inv1 = s1 * s1;
      const float u21 = p21 - p20 * t10, u31 = p31 - p30 * t10;
      const float t21 = u21 * inv1, t31 = u31 * inv1;
      const float d2 = p22 - p20 * t20 - u21 * t21;
      const float s2 = rsqrtf(d2), inv2 = s2 * s2;
      const float u32 = p32 - p30 * t20 - u31 * t21;
      const float t32 = u32 * inv2;
      const float d3 = p33 - p30 * t30 - u31 * t31 - u32 * t32;
      const float s3 = rsqrtf(d3), inv3 = s3 * s3;
      // own-row updated column values
      const float c0i = cb[0][i];
      const float c1i = cb[1][i] - c0i * t10;
      const float c2i = cb[2][i] - c0i * t20 - c1i * t21;
      const float c3i = cb[3][i] - c0i * t30 - c1i * t31 - c2i * t32;
      if (g == 0) {
        float lv0 = (i >= j0    ) ? c0i * s0 : 0.0f;
        float lv1 = (i >= j0 + 1) ? c1i * s1 : 0.0f;
        float lv2 = (i >= j0 + 2) ? c2i * s2 : 0.0f;
        float lv3 = (i >= j0 + 3) ? c3i * s3 : 0.0f;
        sm->Lb[i * LP + j0]     = lv0;
        sm->Lb[i * LP + j0 + 1] = lv1;
        sm->Lb[i * LP + j0 + 2] = lv2;
        sm->Lb[i * LP + j0 + 3] = lv3;
        sm->LbT[(j0    ) * LT + i] = lv0;
        sm->LbT[(j0 + 1) * LT + i] = lv1;
        sm->LbT[(j0 + 2) * LT + i] = lv2;
        sm->LbT[(j0 + 3) * LT + i] = lv3;
        if (i == j0) {
          sm->invd[j0] = s0; sm->invd[j0 + 1] = s1;
          sm->invd[j0 + 2] = s2; sm->invd[j0 + 3] = s3;
        }
      }
      if (gb + 15 > j0 + 3) {          // warp-uniform: group has cols > j0+3
        const float f0 = c0i * inv0, f1 = c1i * inv1;
        const float f2 = c2i * inv2, f3 = c3i * inv3;
        const float4* v0 = (const float4*)&cb[0][gb];
        const float4* v1 = (const float4*)&cb[1][gb];
        const float4* v2 = (const float4*)&cb[2][gb];
        const float4* v3 = (const float4*)&cb[3][gb];
#pragma unroll
        for (int cq = 0; cq < 4; ++cq) {
          float4 x0 = v0[cq], x1 = v1[cq], x2 = v2[cq], x3 = v3[cq];
          const int k = gb + cq * 4;
          if (k + 0 > j0 + 3) {
            float b0 = x0.x, b1 = x1.x - b0*t10, b2 = x2.x - b0*t20 - b1*t21;
            float b3 = x3.x - b0*t30 - b1*t31 - b2*t32;
            a[cq*4+0] -= f0*b0 + f1*b1 + f2*b2 + f3*b3;
          }
          if (k + 1 > j0 + 3) {
            float b0 = x0.y, b1 = x1.y - b0*t10, b2 = x2.y - b0*t20 - b1*t21;
            float b3 = x3.y - b0*t30 - b1*t31 - b2*t32;
            a[cq*4+1] -= f0*b0 + f1*b1 + f2*b2 + f3*b3;
          }
          if (k + 2 > j0 + 3) {
            float b0 = x0.z, b1 = x1.z - b0*t10, b2 = x2.z - b0*t20 - b1*t21;
            float b3 = x3.z - b0*t30 - b1*t31 - b2*t32;
            a[cq*4+2] -= f0*b0 + f1*b1 + f2*b2 + f3*b3;
          }
          if (k + 3 > j0 + 3) {
            float b0 = x0.w, b1 = x1.w - b0*t10, b2 = x2.w - b0*t20 - b1*t21;
            float b3 = x3.w - b0*t30 - b1*t31 - b2*t32;
            a[cq*4+3] -= f0*b0 + f1*b1 + f2*b2 + f3*b3;
          }
        }
      }
    }
  }
}

// Register-resident Li = L^{-1} (lower, exact zeros above diagonal),
// EIGHT pivots per barrier. Thread (c, p:0..3) owns rows [16p,16p+16) of
// column c as deferred residual x[16]. The owning group runs a local 8-step
// forward substitution on the 8x8 pivot block and publishes 8 y's; consumers
// do a rank-8 update from LbT rows. 8 barriers.
__device__ __forceinline__ void triinv64_reg(SmemNLF* sm,
                                             const int c, const int p) {
  const int cw = c & 32;                // warp-uniform
  const int pb = p << 4;
  float x[16];
#pragma unroll
  for (int q = 0; q < 16; ++q) x[q] = ((pb + q) == c) ? 1.0f : 0.0f;
#pragma unroll 1
  for (int jg = 0; jg < 8; ++jg) {
    const int j0 = jg << 3;
    const bool owner = (p == (jg >> 1));
    float (*yb)[72] = sm->ybuf[jg & 1];
    if (owner) {
      const int q0 = (jg & 1) << 3;     // 0 or 8 within the owned 16 rows
      float y[8];
      y[0] = x[q0] * sm->invd[j0];
#pragma unroll
      for (int r = 1; r < 8; ++r) {
        float acc = x[q0 + r];
#pragma unroll
        for (int cc = 0; cc < 8; ++cc)
          if (cc < r) acc -= sm->Lb[(j0 + r) * LP + (j0 + cc)] * y[cc];
        y[r] = acc * sm->invd[j0 + r];
      }
#pragma unroll
      for (int r = 0; r < 8; ++r) {
        yb[r][c] = y[r];
        sm->Li[(j0 + r) * LP + c] = y[r];   // final Li rows (0 above diag)
      }
    }
    __syncthreads();
    if (j0 + 7 >= cw && pb + 15 > j0 + 7) {   // warp-uniform work filter
      float y[8];
#pragma unroll
      for (int r = 0; r < 8; ++r) y[r] = yb[r][c];
#pragma unroll
      for (int rr = 0; rr < 8; ++rr) {
        const float4* lrow = (const float4*)&sm->LbT[(j0 + rr) * LT + pb];
        const float yr = y[rr];
#pragma unroll
        for (int cq = 0; cq < 4; ++cq) {
          float4 lv = lrow[cq];
          const int rb = pb + cq * 4;
          if (rb + 0 > j0 + 7) x[cq*4+0] -= lv.x * yr;
          if (rb + 1 > j0 + 7) x[cq*4+1] -= lv.y * yr;
          if (rb + 2 > j0 + 7) x[cq*4+2] -= lv.z * yr;
          if (rb + 3 > j0 + 7) x[cq*4+3] -= lv.w * yr;
        }
      }
    }
  }
}

__device__ __forceinline__ void load_step(SmemNLF* sm,
    const float* __restrict__ gk, const float* __restrict__ gK,
    const float* __restrict__ gw, int b, int t, int tid) {
  if (tid < L_DIM)
    sm->kt[tid] = gk[((size_t)b * T_DIM + t) * L_DIM + tid];
  {
    const float4* src =
        (const float4*)(gK + ((size_t)b * T_DIM + t) * (L_DIM * R_DIM));
    float4 v = src[tid];
    int l = tid >> 2, r = (tid & 3) * 4;
    float* dst = &sm->Ksm[l * KP + r];
    dst[0] = v.x; dst[1] = v.y; dst[2] = v.z; dst[3] = v.w;
  }
  {
    int s = tid >> 4, l4 = (tid & 15) * 4;
    const float4* src = (const float4*)(
        gw + (((size_t)t * S_DIM + s) * B_DIM + b) * L_DIM + l4);
    *(float4*)&sm->wsm[s * L_DIM + l4] = *src;
  }
}

// z_f[s][i] = mf[i] + sum_j Li[j][i]*w[s][j]; writes zs and z_f output.
__device__ __forceinline__ void zf_store(SmemNLF* sm, float* __restrict__ out_z,
                                         int b, int t, int tid) {
  const int i = tid & 63, p = tid >> 6;
  const float base = sm->mf[i];
  float a0 = base, a1 = base, a2 = base, a3 = base;
  const float* wr0 = &sm->wsm[(4 * p + 0) * L_DIM];
  const float* wr1 = &sm->wsm[(4 * p + 1) * L_DIM];
  const float* wr2 = &sm->wsm[(4 * p + 2) * L_DIM];
  const float* wr3 = &sm->wsm[(4 * p + 3) * L_DIM];
  const int j0 = i & 32;
  for (int j = j0; j < 64; ++j) {
    float lv = sm->Li[j * LP + i];
    a0 += lv * wr0[j]; a1 += lv * wr1[j];
    a2 += lv * wr2[j]; a3 += lv * wr3[j];
  }
  float acc[4] = {a0, a1, a2, a3};
#pragma unroll
  for (int q = 0; q < 4; ++q) {
    int s = 4 * p + q;
    sm->zs[s * L_DIM + i] = acc[q];
    out_z[(((size_t)s * B_DIM + b) * T_DIM + t) * L_DIM + i] = acc[q];
  }
}

extern __shared__ float smem_raw_nlf[];

__global__ void __launch_bounds__(NT, 1)
NonlinearFilter_24721831756601_kernel(
    const float* __restrict__ gk, const float* __restrict__ gK,
    const float* __restrict__ glogQ, const float* __restrict__ gm0,
    const float* __restrict__ glogv0, const float* __restrict__ gW1,
    const float* __restrict__ gb1, const float* __restrict__ gW2,
    const float* __restrict__ gb2, const float* __restrict__ gw,
    float* __restrict__ out) {
  SmemNLF* sm = (SmemNLF*)smem_raw_nlf;
  const int tid = threadIdx.x;
  const int b = blockIdx.x;
  const int i = tid & 63;             // owned row (chol) / column (triinv)
  const int g = tid >> 6;             // group 0..3
  const int gb = g << 4;
  const int iw = i & 32;              // warp-uniform floor of i

  const size_t ZN = (size_t)S_DIM * B_DIM * T_DIM * L_DIM;
  const size_t MN = (size_t)B_DIM * T_DIM * L_DIM;
  const size_t PN = (size_t)B_DIM * T_DIM * L_DIM * L_DIM;
  float* out_z  = out;
  float* out_mf = out + ZN;
  float* out_mp = out_mf + MN;
  float* out_Pf = out_mp + MN;
  float* out_Pp = out_Pf + PN;

  for (int idx = tid; idx < L_DIM * H_DIM; idx += NT) sm->w1[idx] = gW1[idx];
  for (int idx = tid; idx < H_DIM * L_DIM; idx += NT) sm->w2[idx] = gW2[idx];
  if (tid < H_DIM) sm->b1[tid] = gb1[tid];
  if (tid < L_DIM) {
    sm->b2[tid]  = gb2[tid];
    sm->Qs[tid]  = softplus_f(glogQ[tid]);
    float p0     = softplus_f(glogv0[tid]);
    sm->J0s[tid] = 1.0f / p0;
    sm->sqP0[tid] = sqrtf(p0);
    sm->m0s[tid] = gm0[tid];
  }
  load_step(sm, gk, gK, gw, b, 0, tid);
  __syncthreads();

  float a[16];                         // register tile A[i][16g+q]

  // ================= t = 0 =================
  {
    float Ki[R_DIM];
#pragma unroll
    for (int r = 0; r < R_DIM; ++r) Ki[r] = sm->Ksm[i * KP + r];
#pragma unroll
    for (int q = 0; q < 16; ++q) {
      int jj = gb + q;
      float acc = (i == jj) ? sm->J0s[i] : 0.0f;
#pragma unroll
      for (int r = 0; r < R_DIM; ++r) acc += Ki[r] * sm->Ksm[jj * KP + r];
      a[q] = acc;
    }
    if (tid < L_DIM)
      sm->hf[tid] = sm->J0s[tid] * sm->m0s[tid] + sm->kt[tid];

    chol64_reg(a, sm, i, g);           // Lf0
    triinv64_reg(sm, i, g);            // Li = Lf0^{-1}

    if (tid < L_DIM) {
      float acc = 0.0f;
      int jend = (tid | 31) + 1;
      for (int j = 0; j < jend; ++j) acc += sm->Li[tid * LP + j] * sm->hf[j];
      sm->yv[tid] = acc;
      out_mp[((size_t)b * T_DIM + 0) * L_DIM + tid] = sm->m0s[tid];
    }
    {
      float* dst = out_Pp + ((size_t)b * T_DIM + 0) * (L_DIM * L_DIM);
      for (int idx = tid; idx < 64 * 64; idx += NT) {
        int r = idx >> 6, c2 = idx & 63;
        dst[idx] = (r == c2) ? sm->sqP0[r] : 0.0f;
      }
    }
    __syncthreads();
    if (tid < L_DIM) {
      float acc = 0.0f;
      for (int j = iw; j < 64; ++j) acc += sm->Li[j * LP + tid] * sm->yv[j];
      sm->mf[tid] = acc;
      out_mf[((size_t)b * T_DIM + 0) * L_DIM + tid] = acc;
    }
    {
      float* dst = out_Pf + ((size_t)b * T_DIM + 0) * (L_DIM * L_DIM);
      for (int idx = tid; idx < 64 * 64; idx += NT) {
        int r = idx >> 6, c2 = idx & 63;
        dst[idx] = sm->Li[c2 * LP + r];
      }
    }
    __syncthreads();
    zf_store(sm, out_z, b, 0, tid);
    __syncthreads();
  }

  // ================= t = 1 .. T-1 =================
  for (int t = 1; t < T_DIM; ++t) {
    load_step(sm, gk, gK, gw, b, t, tid);

    // ---- MLP layer 1 ----
    {
      float acc[S_DIM];
      float bb = sm->b1[tid];
#pragma unroll
      for (int s = 0; s < S_DIM; ++s) acc[s] = bb;
      for (int l = 0; l < L_DIM; l += 4) {
        float wa = sm->w1[(l + 0) * H_DIM + tid];
        float wb = sm->w1[(l + 1) * H_DIM + tid];
        float wc = sm->w1[(l + 2) * H_DIM + tid];
        float wd = sm->w1[(l + 3) * H_DIM + tid];
#pragma unroll
        for (int s = 0; s < S_DIM; ++s) {
          float4 z4 = *(const float4*)&sm->zs[s * L_DIM + l];
          acc[s] += z4.x * wa + z4.y * wb + z4.z * wc + z4.w * wd;
        }
      }
#pragma unroll
      for (int s = 0; s < S_DIM; ++s) sm->hid[s * HS + tid] = tanhf(acc[s]);
    }
    __syncthreads();

    // ---- MLP layer 2 ----
    {
      const int j = tid & 63, p = tid >> 6;
      float acc4[4];
      float bb = sm->b2[j];
#pragma unroll
      for (int q = 0; q < 4; ++q) acc4[q] = bb;
      for (int h = 0; h < H_DIM; h += 4) {
        float wa = sm->w2[(h + 0) * L_DIM + j];
        float wb = sm->w2[(h + 1) * L_DIM + j];
        float wc = sm->w2[(h + 2) * L_DIM + j];
        float wd = sm->w2[(h + 3) * L_DIM + j];
#pragma unroll
        for (int q = 0; q < 4; ++q) {
          float4 h4 = *(const float4*)&sm->hid[(4 * p + q) * HS + h];
          acc4[q] += h4.x * wa + h4.y * wb + h4.z * wc + h4.w * wd;
        }
      }
#pragma unroll
      for (int q = 0; q < 4; ++q) sm->ms[(4 * p + q) * L_DIM + j] = acc4[q];
    }
    __syncthreads();

    // ---- m_p ----
    if (tid < L_DIM) {
      float acc = 0.0f;
#pragma unroll
      for (int s = 0; s < S_DIM; ++s) acc += sm->ms[s * L_DIM + tid];
      sm->mp[tid] = acc * (1.0f / (float)S_DIM);
    }
    __syncthreads();

    // ---- P_p into registers: a[q] = Q_diag + Ezz - mp mp^T ----
    {
      const float* msb = &sm->ms[gb];
#pragma unroll
      for (int q = 0; q < 16; ++q) a[q] = 0.0f;
#pragma unroll
      for (int s = 0; s < S_DIM; ++s) {
        float msi = sm->ms[s * L_DIM + i];
        const float4* m4 = (const float4*)&msb[s * L_DIM];
        float mj[16];
        *(float4*)&mj[0]  = m4[0];
        *(float4*)&mj[4]  = m4[1];
        *(float4*)&mj[8]  = m4[2];
        *(float4*)&mj[12] = m4[3];
#pragma unroll
        for (int q = 0; q < 16; ++q) a[q] += msi * mj[q];
      }
      float mpi = sm->mp[i];
#pragma unroll
      for (int q = 0; q < 16; ++q) {
        int jj = gb + q;
        a[q] = a[q] * (1.0f / (float)S_DIM) - mpi * sm->mp[jj];
        if (i == jj) a[q] += sm->Qs[i];
      }
    }

    chol64_reg(a, sm, i, g);           // Lp
    triinv64_reg(sm, i, g);            // Li = Lp^{-1}

    // yv = Li*mp ; outputs m_p, P_p_chol (=Lb)
    if (tid < L_DIM) {
      float acc = 0.0f;
      int jend = (tid | 31) + 1;
      for (int j = 0; j < jend; ++j) acc += sm->Li[tid * LP + j] * sm->mp[j];
      sm->yv[tid] = acc;
      out_mp[((size_t)b * T_DIM + t) * L_DIM + tid] = sm->mp[tid];
    }
    {
      float* dst = out_Pp + ((size_t)b * T_DIM + t) * (L_DIM * L_DIM);
      for (int idx = tid; idx < 64 * 64; idx += NT) {
        int r = idx >> 6, c2 = idx & 63;
        dst[idx] = sm->Lb[r * LP + c2];
      }
    }
    __syncthreads();

    // hf = Li^T yv + k_t ; J_f = Li^T Li + K K^T into registers
    if (tid < L_DIM) {
      float acc = sm->kt[tid];
      for (int j = iw; j < 64; ++j) acc += sm->Li[j * LP + tid] * sm->yv[j];
      sm->hf[tid] = acc;
    }
    {
      float Ki[R_DIM];
#pragma unroll
      for (int r = 0; r < R_DIM; ++r) Ki[r] = sm->Ksm[i * KP + r];
#pragma unroll
      for (int q = 0; q < 16; ++q) {
        int jj = gb + q;
        float acc = 0.0f;
#pragma unroll
        for (int r = 0; r < R_DIM; ++r) acc += Ki[r] * sm->Ksm[jj * KP + r];
        a[q] = acc;
      }
      int k0 = (iw > gb) ? iw : gb;    // warp-uniform; zeros skipped
      for (int k2 = k0; k2 < 64; ++k2) {
        float lvi = sm->Li[k2 * LP + i];
        const float* lr = &sm->Li[k2 * LP + gb];
#pragma unroll
        for (int q = 0; q < 16; ++q) a[q] += lvi * lr[q];
      }
    }
    __syncthreads();

    chol64_reg(a, sm, i, g);           // Lf
    triinv64_reg(sm, i, g);            // Li = Lf^{-1}

    // yv = Li*hf ; P_f_chol = Li^T
    if (tid < L_DIM) {
      float acc = 0.0f;
      int jend = (tid | 31) + 1;
      for (int j = 0; j < jend; ++j) acc += sm->Li[tid * LP + j] * sm->hf[j];
      sm->yv[tid] = acc;
    }
    {
      float* dst = out_Pf + ((size_t)b * T_DIM + t) * (L_DIM * L_DIM);
      for (int idx = tid; idx < 64 * 64; idx += NT) {
        int r = idx >> 6, c2 = idx & 63;
        dst[idx] = sm->Li[c2 * LP + r];
      }
    }
    __syncthreads();

    // mf = Li^T yv
    if (tid < L_DIM) {
      float acc = 0.0f;
      for (int j = iw; j < 64; ++j) acc += sm->Li[j * LP + tid] * sm->yv[j];
      sm->mf[tid] = acc;
      out_mf[((size_t)b * T_DIM + t) * L_DIM + tid] = acc;
    }
    __syncthreads();

    zf_store(sm, out_z, b, t, tid);
    __syncthreads();
  }
}

extern "C" void kernel_launch(void* const* d_in, const int* in_sizes, int n_in,
                              void* d_out, int out_size) {
  (void)in_sizes; (void)n_in; (void)out_size;
  static int attr_set = 0;
  if (!attr_set) {
    cudaFuncSetAttribute(NonlinearFilter_24721831756601_kernel,
                         cudaFuncAttributeMaxDynamicSharedMemorySize,
                         (int)sizeof(SmemNLF));
    attr_set = 1;
  }
  NonlinearFilter_24721831756601_kernel
      <<<B_DIM, NT, sizeof(SmemNLF)>>>(
          (const float*)d_in[0], (const float*)d_in[1],
          (const float*)d_in[2], (const float*)d_in[3],
          (const float*)d_in[4], (const float*)d_in[5],
          (const float*)d_in[6], (const float*)d_in[7],
          (const float*)d_in[8], (const float*)d_in[9],
          (float*)d_out);
}

// round 17
// speedup vs baseline: 1.1385x; 1.1385x over previous
#include <cuda_runtime.h>
#include <math.h>

#define S_DIM 16
#define B_DIM 128
#define T_DIM 200
#define L_DIM 64
#define R_DIM 16
#define H_DIM 256
#define NT    256
#define LP    65    // padded stride, 64x64 matrices
#define HS    260   // padded stride for hidden
#define KP    17    // padded stride for 64x16 tiles

struct __align__(16) SmemNLF {
  float w1[L_DIM * H_DIM];
  float w2[H_DIM * L_DIM];
  float b1[H_DIM];
  float b2[L_DIM];
  float zs[S_DIM * L_DIM];
  float hid[S_DIM * HS];
  float ms[S_DIM * L_DIM];
  float Pp[L_DIM * LP];      // P_p; after revchol holds U = P_f_chol
  float Lb[L_DIM * LP];      // Lp = chol(P_p), zeros above diag
  float Ksm[L_DIM * KP];     // K_t (L,R)
  float Wsm[L_DIM * KP];     // W = P_p K
  float Ysm[L_DIM * KP];     // Y = W * Li16^T
  float wsm[S_DIM * L_DIM];  // w_t
  float colbuf[2][144];      // rank-2 chol column broadcast (double buffered)
  float Msm[16 * 17];        // M = I + K^T W
  float L16[16 * 17];        // chol(M), zeros above diag
  float Li16[16 * 17];       // L16^{-1}, zeros above diag
  float pfk[4 * 68];         // partial P_f * vec
  float svec[16], uvec[16], t2v[16];
  float wv[L_DIM];           // W * t2
  float kt[L_DIM], mp[L_DIM], hf[L_DIM], mf[L_DIM];
  float Qs[L_DIM], m0s[L_DIM], J0s[L_DIM], Ps0[L_DIM], sqP0[L_DIM];
};

__device__ __forceinline__ float softplus_f(float x) {
  return fmaxf(x, 0.0f) + log1pf(expf(-fabsf(x)));
}

// Register-resident rank-2 right-looking Cholesky (the proven R12 kernel).
// Thread (i, g:0..3) owns A[i][16g+q] in a[16]. 32 barriers.
// REV=false: factors A, stores L (zeros above diag) into Lout.
// REV=true : 'a' holds the index-REVERSED matrix Ã[i][j]=P[63-i][63-j];
//            stores U[63-i][63-j] = L̃[i][j], i.e. the unique upper-triangular
//            U with U U^T = P (zeros below diag).
template <bool REV>
__device__ __forceinline__ void chol64_rank2(float* a, SmemNLF* sm,
                                             float* Lout,
                                             const int i, const int g) {
  const int gb = g << 4;
#pragma unroll 1
  for (int jg = 0; jg < 4; ++jg) {
    const bool owner = (g == jg);
#pragma unroll
    for (int q = 0; q < 16; q += 2) {
      const int j = (jg << 4) + q;
      float* cb = sm->colbuf[(q >> 1) & 1];
      if (owner) { cb[i] = a[q]; cb[72 + i] = a[q + 1]; }
      __syncthreads();
      const float d0   = cb[j];
      const float s0   = rsqrtf(d0);
      const float inv0 = s0 * s0;
      const float tl   = cb[j + 1] * inv0;
      const float d1   = cb[72 + j + 1] - cb[j + 1] * tl;
      const float s1   = rsqrtf(d1);
      const float inv1 = s1 * s1;
      if (g == 0) {
        float c0i = cb[i];
        float c1i = cb[72 + i] - c0i * tl;
        float lv0 = (i >= j)     ? c0i * s0 : 0.0f;
        float lv1 = (i >= j + 1) ? c1i * s1 : 0.0f;
        if (REV) {
          Lout[(63 - i) * LP + (63 - j)] = lv0;
          Lout[(63 - i) * LP + (62 - j)] = lv1;
        } else {
          Lout[i * LP + j]     = lv0;
          Lout[i * LP + j + 1] = lv1;
        }
      }
      if (gb + 15 > j + 1) {           // warp-uniform: group has cols > j+1
        float c0i = cb[i];
        float c1i = cb[72 + i] - c0i * tl;
        float f0  = c0i * inv0;
        float f1  = c1i * inv1;
        const float4* v0 = (const float4*)&cb[gb];
        const float4* v1 = (const float4*)&cb[72 + gb];
#pragma unroll
        for (int cq = 0; cq < 4; ++cq) {
          float4 x0 = v0[cq];
          float4 x1 = v1[cq];
          const int k = gb + cq * 4;
          float u;
          if (k + 0 > j + 1) { u = x1.x - x0.x * tl; a[cq*4+0] -= f0 * x0.x + f1 * u; }
          if (k + 1 > j + 1) { u = x1.y - x0.y * tl; a[cq*4+1] -= f0 * x0.y + f1 * u; }
          if (k + 2 > j + 1) { u = x1.z - x0.z * tl; a[cq*4+2] -= f0 * x0.z + f1 * u; }
          if (k + 3 > j + 1) { u = x1.w - x0.w * tl; a[cq*4+3] -= f0 * x0.w + f1 * u; }
        }
      }
    }
  }
}

__device__ __forceinline__ void load_step(SmemNLF* sm,
    const float* __restrict__ gk, const float* __restrict__ gK,
    const float* __restrict__ gw, int b, int t, int tid) {
  if (tid < L_DIM)
    sm->kt[tid] = gk[((size_t)b * T_DIM + t) * L_DIM + tid];
  {
    const float4* src =
        (const float4*)(gK + ((size_t)b * T_DIM + t) * (L_DIM * R_DIM));
    float4 v = src[tid];
    int l = tid >> 2, r = (tid & 3) * 4;
    float* dst = &sm->Ksm[l * KP + r];
    dst[0] = v.x; dst[1] = v.y; dst[2] = v.z; dst[3] = v.w;
  }
  {
    int s = tid >> 4, l4 = (tid & 15) * 4;
    const float4* src = (const float4*)(
        gw + (((size_t)t * S_DIM + s) * B_DIM + b) * L_DIM + l4);
    *(float4*)&sm->wsm[s * L_DIM + l4] = *src;
  }
}

// z_f[s][i] = mf[i] + sum_{j>=i} U[i][j] * w[s][j]  (U upper, zeros below)
__device__ __forceinline__ void zf_store(SmemNLF* sm, const float* __restrict__ U,
                                         float* __restrict__ out_z,
                                         int b, int t, int tid) {
  const int i = tid & 63, p = tid >> 6;
  const float base = sm->mf[i];
  float a0 = base, a1 = base, a2 = base, a3 = base;
  const float* wr0 = &sm->wsm[(4 * p + 0) * L_DIM];
  const float* wr1 = &sm->wsm[(4 * p + 1) * L_DIM];
  const float* wr2 = &sm->wsm[(4 * p + 2) * L_DIM];
  const float* wr3 = &sm->wsm[(4 * p + 3) * L_DIM];
  const int j0 = i & 32;               // warp-uniform; U[i][j]==0 for j<i
  for (int j = j0; j < 64; ++j) {
    float uv = U[i * LP + j];
    a0 += uv * wr0[j]; a1 += uv * wr1[j];
    a2 += uv * wr2[j]; a3 += uv * wr3[j];
  }
  float acc[4] = {a0, a1, a2, a3};
#pragma unroll
  for (int q = 0; q < 4; ++q) {
    int s = 4 * p + q;
    sm->zs[s * L_DIM + i] = acc[q];
    out_z[(((size_t)s * B_DIM + b) * T_DIM + t) * L_DIM + i] = acc[q];
  }
}

extern __shared__ float smem_raw_nlf[];

__global__ void __launch_bounds__(NT, 1)
NonlinearFilter_24721831756601_kernel(
    const float* __restrict__ gk, const float* __restrict__ gK,
    const float* __restrict__ glogQ, const float* __restrict__ gm0,
    const float* __restrict__ glogv0, const float* __restrict__ gW1,
    const float* __restrict__ gb1, const float* __restrict__ gW2,
    const float* __restrict__ gb2, const float* __restrict__ gw,
    float* __restrict__ out) {
  SmemNLF* sm = (SmemNLF*)smem_raw_nlf;
  const int tid = threadIdx.x;
  const int b = blockIdx.x;
  const int i = tid & 63;
  const int g = tid >> 6;
  const int gb = g << 4;

  const size_t ZN = (size_t)S_DIM * B_DIM * T_DIM * L_DIM;
  const size_t MN = (size_t)B_DIM * T_DIM * L_DIM;
  const size_t PN = (size_t)B_DIM * T_DIM * L_DIM * L_DIM;
  float* out_z  = out;
  float* out_mf = out + ZN;
  float* out_mp = out_mf + MN;
  float* out_Pf = out_mp + MN;
  float* out_Pp = out_Pf + PN;

  for (int idx = tid; idx < L_DIM * H_DIM; idx += NT) sm->w1[idx] = gW1[idx];
  for (int idx = tid; idx < H_DIM * L_DIM; idx += NT) sm->w2[idx] = gW2[idx];
  if (tid < H_DIM) sm->b1[tid] = gb1[tid];
  if (tid < L_DIM) {
    sm->b2[tid]  = gb2[tid];
    sm->Qs[tid]  = softplus_f(glogQ[tid]);
    float p0     = softplus_f(glogv0[tid]);
    sm->J0s[tid] = 1.0f / p0;
    sm->Ps0[tid] = p0;
    sm->sqP0[tid] = sqrtf(p0);
    sm->m0s[tid] = gm0[tid];
  }
  __syncthreads();

  float a[16];

#pragma unroll 1
  for (int t = 0; t < T_DIM; ++t) {
    const bool t0 = (t == 0);
    load_step(sm, gk, gK, gw, b, t, tid);

    if (!t0) {
      // ---- MLP layer 1 ----
      {
        float acc[S_DIM];
        float bb = sm->b1[tid];
#pragma unroll
        for (int s = 0; s < S_DIM; ++s) acc[s] = bb;
        for (int l = 0; l < L_DIM; l += 4) {
          float wa = sm->w1[(l + 0) * H_DIM + tid];
          float wb = sm->w1[(l + 1) * H_DIM + tid];
          float wc = sm->w1[(l + 2) * H_DIM + tid];
          float wd = sm->w1[(l + 3) * H_DIM + tid];
#pragma unroll
          for (int s = 0; s < S_DIM; ++s) {
            float4 z4 = *(const float4*)&sm->zs[s * L_DIM + l];
            acc[s] += z4.x * wa + z4.y * wb + z4.z * wc + z4.w * wd;
          }
        }
#pragma unroll
        for (int s = 0; s < S_DIM; ++s) sm->hid[s * HS + tid] = tanhf(acc[s]);
      }
      __syncthreads();

      // ---- MLP layer 2 ----
      {
        float acc4[4];
        float bb = sm->b2[i];
#pragma unroll
        for (int q = 0; q < 4; ++q) acc4[q] = bb;
        for (int h = 0; h < H_DIM; h += 4) {
          float wa = sm->w2[(h + 0) * L_DIM + i];
          float wb = sm->w2[(h + 1) * L_DIM + i];
          float wc = sm->w2[(h + 2) * L_DIM + i];
          float wd = sm->w2[(h + 3) * L_DIM + i];
#pragma unroll
          for (int q = 0; q < 4; ++q) {
            float4 h4 = *(const float4*)&sm->hid[(4 * g + q) * HS + h];
            acc4[q] += h4.x * wa + h4.y * wb + h4.z * wc + h4.w * wd;
          }
        }
#pragma unroll
        for (int q = 0; q < 4; ++q) sm->ms[(4 * g + q) * L_DIM + i] = acc4[q];
      }
      __syncthreads();

      // ---- m_p ----
      if (tid < L_DIM) {
        float acc = 0.0f;
#pragma unroll
        for (int s = 0; s < S_DIM; ++s) acc += sm->ms[s * L_DIM + tid];
        sm->mp[tid] = acc * (1.0f / (float)S_DIM);
      }
      __syncthreads();

      // ---- P_p into registers + SMEM ----
      {
        const float* msb = &sm->ms[gb];
#pragma unroll
        for (int q = 0; q < 16; ++q) a[q] = 0.0f;
#pragma unroll
        for (int s = 0; s < S_DIM; ++s) {
          float msi = sm->ms[s * L_DIM + i];
          const float4* m4 = (const float4*)&msb[s * L_DIM];
          float mj[16];
          *(float4*)&mj[0]  = m4[0];
          *(float4*)&mj[4]  = m4[1];
          *(float4*)&mj[8]  = m4[2];
          *(float4*)&mj[12] = m4[3];
#pragma unroll
          for (int q = 0; q < 16; ++q) a[q] += msi * mj[q];
        }
        float mpi = sm->mp[i];
#pragma unroll
        for (int q = 0; q < 16; ++q) {
          int jj = gb + q;
          a[q] = a[q] * (1.0f / (float)S_DIM) - mpi * sm->mp[jj];
          if (i == jj) a[q] += sm->Qs[i];
          sm->Pp[i * LP + jj] = a[q];
        }
      }
      __syncthreads();

      // ---- Lp = chol(P_p) (for the P_p_chol output only) ----
      chol64_rank2<false>(a, sm, sm->Lb, i, g);
    } else {
      // t = 0: P_p = diag(P0); h_f0 = J0*m0 + k0
      for (int idx = tid; idx < 64 * 64; idx += NT) {
        int r = idx >> 6, c2 = idx & 63;
        sm->Pp[r * LP + c2] = (r == c2) ? sm->Ps0[r] : 0.0f;
      }
      if (tid < L_DIM)
        sm->hf[tid] = sm->J0s[tid] * sm->m0s[tid] + sm->kt[tid];
      __syncthreads();
    }

    // ---- W = P_p K  (thread (i,g): W[i][4g..4g+3]) ----
    {
      float w4[4] = {0.0f, 0.0f, 0.0f, 0.0f};
      const int r0 = g * 4;
      for (int j = 0; j < L_DIM; ++j) {
        float pv = sm->Pp[i * LP + j];
        const float* kr = &sm->Ksm[j * KP + r0];
        w4[0] += pv * kr[0]; w4[1] += pv * kr[1];
        w4[2] += pv * kr[2]; w4[3] += pv * kr[3];
      }
#pragma unroll
      for (int r = 0; r < 4; ++r) sm->Wsm[i * KP + r0 + r] = w4[r];
    }
    __syncthreads();

    // ---- M = I + K^T W  (one entry per thread) ; svec = K^T m_p ----
    {
      const int r = tid >> 4, c = tid & 15;
      float acc = (r == c) ? 1.0f : 0.0f;
      for (int j = 0; j < L_DIM; ++j)
        acc += sm->Ksm[j * KP + r] * sm->Wsm[j * KP + c];
      sm->Msm[r * 17 + c] = acc;
      if (!t0 && tid < 16) {
        float sa = 0.0f;
        for (int j = 0; j < L_DIM; ++j)
          sa += sm->Ksm[j * KP + tid] * sm->mp[j];
        sm->svec[tid] = sa;
      }
    }
    __syncthreads();

    // ---- warp 0: chol16(M), Li16 = L16^{-1}, t2 = M^{-1} svec.
    //      warps 1-7: stream P_p_chol + m_p outputs to GMEM. ----
    if (tid < 32) {
      const int r16 = tid & 15;
      float mrow[16];
#pragma unroll
      for (int c = 0; c < 16; ++c) mrow[c] = sm->Msm[r16 * 17 + c];
      float invd16[16];
#pragma unroll
      for (int j = 0; j < 16; ++j) {
        float colj = mrow[j];
        float d = __shfl_sync(0xffffffffu, colj, j);
        float s = rsqrtf(d);
        invd16[j] = s;
        if (tid < 16) sm->L16[r16 * 17 + j] = (r16 >= j) ? colj * s : 0.0f;
        float f = colj * (s * s);
#pragma unroll
        for (int k = j + 1; k < 16; ++k) {
          float ckj = __shfl_sync(0xffffffffu, colj, k);
          mrow[k] -= f * ckj;
        }
      }
      __syncwarp();
      // triinv16: lane c owns column c (deferred-free direct form)
      float x16[16];
#pragma unroll
      for (int q = 0; q < 16; ++q) x16[q] = (q == r16) ? 1.0f : 0.0f;
#pragma unroll
      for (int j = 0; j < 16; ++j) {
        float yj = x16[j] * invd16[j];
        if (tid < 16) sm->Li16[j * 17 + r16] = yj;
#pragma unroll
        for (int k = j + 1; k < 16; ++k)
          x16[k] -= sm->L16[k * 17 + j] * yj;
      }
      __syncwarp();
      if (!t0 && tid < 16) {
        float acc = 0.0f;
#pragma unroll
        for (int c = 0; c < 16; ++c)
          acc += sm->Li16[r16 * 17 + c] * sm->svec[c];
        sm->uvec[r16] = acc;
      }
      __syncwarp();
      if (!t0 && tid < 16) {
        float acc = 0.0f;
#pragma unroll
        for (int j = 0; j < 16; ++j)
          acc += sm->Li16[j * 17 + r16] * sm->uvec[j];
        sm->t2v[r16] = acc;
      }
    } else {
      float* dstPp = out_Pp + ((size_t)b * T_DIM + t) * (L_DIM * L_DIM);
      if (!t0) {
        for (int idx = tid - 32; idx < 64 * 64; idx += NT - 32) {
          int r = idx >> 6, c2 = idx & 63;
          dstPp[idx] = sm->Lb[r * LP + c2];
        }
        if (tid >= 32 && tid < 96)
          out_mp[((size_t)b * T_DIM + t) * L_DIM + (tid - 32)] = sm->mp[tid - 32];
      } else {
        for (int idx = tid - 32; idx < 64 * 64; idx += NT - 32) {
          int r = idx >> 6, c2 = idx & 63;
          dstPp[idx] = (r == c2) ? sm->sqP0[r] : 0.0f;
        }
        if (tid >= 32 && tid < 96)
          out_mp[((size_t)b * T_DIM + t) * L_DIM + (tid - 32)] = sm->m0s[tid - 32];
      }
    }
    __syncthreads();

    // ---- Y = W Li16^T ; wv = W t2 ----
    {
      float wrow[16];
#pragma unroll
      for (int c = 0; c < 16; ++c) wrow[c] = sm->Wsm[i * KP + c];
      const int r0 = g * 4;
#pragma unroll
      for (int rr = 0; rr < 4; ++rr) {
        const int r = r0 + rr;
        float acc = 0.0f;
#pragma unroll
        for (int c = 0; c < 16; ++c) acc += wrow[c] * sm->Li16[r * 17 + c];
        sm->Ysm[i * KP + r] = acc;
      }
      if (!t0 && tid < L_DIM) {
        float acc = 0.0f;
#pragma unroll
        for (int r = 0; r < 16; ++r) acc += sm->Wsm[tid * KP + r] * sm->t2v[r];
        sm->wv[tid] = acc;
      }
    }
    __syncthreads();

    // ---- P_f (index-REVERSED register tile) + partial P_f*vec ----
    {
      const int ii = 63 - i;
      float Yp[16];
#pragma unroll
      for (int r = 0; r < 16; ++r) Yp[r] = sm->Ysm[ii * KP + r];
      const float* pv = t0 ? sm->hf : sm->kt;
      float pk = 0.0f;
#pragma unroll
      for (int q = 0; q < 16; ++q) {
        const int jj = 63 - gb - q;
        float acc = sm->Pp[ii * LP + jj];
        const float* yr = &sm->Ysm[jj * KP];
#pragma unroll
        for (int r = 0; r < 16; ++r) acc -= Yp[r] * yr[r];
        a[q] = acc;
        pk += acc * pv[jj];
      }
      sm->pfk[g * 68 + ii] = pk;
    }

    // ---- U = revchol(P_f) into Pp (aliased); = P_f_chol ----
    chol64_rank2<true>(a, sm, sm->Pp, i, g);

    // ---- m_f ----
    if (tid < L_DIM) {
      float acc = t0 ? 0.0f : (sm->mp[tid] - sm->wv[tid]);
#pragma unroll
      for (int gg = 0; gg < 4; ++gg) acc += sm->pfk[gg * 68 + tid];
      sm->mf[tid] = acc;
      out_mf[((size_t)b * T_DIM + t) * L_DIM + tid] = acc;
    }
    __syncthreads();

    // ---- z_f + P_f_chol output ----
    zf_store(sm, sm->Pp, out_z, b, t, tid);
    {
      float* dst = out_Pf + ((size_t)b * T_DIM + t) * (L_DIM * L_DIM);
      for (int idx = tid; idx < 64 * 64; idx += NT) {
        int r = idx >> 6, c2 = idx & 63;
        dst[idx] = sm->Pp[r * LP + c2];
      }
    }
    __syncthreads();
  }
}

extern "C" void kernel_launch(void* const* d_in, const int* in_sizes, int n_in,
                              void* d_out, int out_size) {
  (void)in_sizes; (void)n_in; (void)out_size;
  static int attr_set = 0;
  if (!attr_set) {
    cudaFuncSetAttribute(NonlinearFilter_24721831756601_kernel,
                         cudaFuncAttributeMaxDynamicSharedMemorySize,
                         (int)sizeof(SmemNLF));
    attr_set = 1;
  }
  NonlinearFilter_24721831756601_kernel
      <<<B_DIM, NT, sizeof(SmemNLF)>>>(
          (const float*)d_in[0], (const float*)d_in[1],
          (const float*)d_in[2], (const float*)d_in[3],
          (const float*)d_in[4], (const float*)d_in[5],
          (const float*)d_in[6], (const float*)d_in[7],
          (const float*)d_in[8], (const float*)d_in[9],
          (float*)d_out);
}